// round 10
// baseline (speedup 1.0000x reference)
#include <cuda_runtime.h>
#include <cuda_bf16.h>
#include <math_constants.h>

#define NPTS 16384
#define MCTR 4096
#define KNBR 32
#define FIN  64
#define RAD2 0.25f
#define MAXC 64

#define CLS  16      // FPS cluster size (CTAs) — nonportable 16-CTA cluster
#define TFPS 256     // threads per FPS CTA
#define PPT  4       // points per thread; CLS*TFPS*PPT == NPTS
#define NW   (TFPS / 32)
#define NSLOT (CLS * NW)   // 128 warp-key slots per parity

// ---------------- device scratch (no allocations allowed) ----------------
__device__ int g_idx[MCTR];
__device__ int g_nbr[MCTR * KNBR];
__device__ int g_cnt[MCTR];

__device__ __forceinline__ unsigned smem_u32(const void* p)
{
    unsigned a;
    asm("{ .reg .u64 t; cvta.to.shared.u64 t, %1; cvt.u32.u64 %0, t; }"
        : "=r"(a) : "l"(p));
    return a;
}

// ---------------- Stage 1: cluster-cooperative FPS, direct warp-key exchange ----------------
// key = bits(val)<<32 | (0x3FFF - idx)<<12 | tag(12 bits = iteration)
// All warps symmetric: warp-REDUX -> push warp key to all 16 CTAs -> poll 128
// local slots (4 contiguous per lane, vector LDS) -> reduce -> center lookup.
__global__ __launch_bounds__(TFPS, 1) __cluster_dims__(CLS, 1, 1)
void fps_kernel(const float* __restrict__ pos)
{
    extern __shared__ float s_tab[];
    float* s_x = s_tab;
    float* s_y = s_tab + NPTS;
    float* s_z = s_tab + 2 * NPTS;

    __shared__ unsigned long long s_mbox[2][NSLOT];  // [parity][srcCTA*NW + srcWarp]

    const int t    = threadIdx.x;
    const int w    = t >> 5;
    const int lane = t & 31;
    unsigned rank;
    asm("mov.u32 %0, %%cluster_ctarank;" : "=r"(rank));

    // one-time: local coordinate table + mailbox init
    for (int i = t; i < NPTS; i += TFPS) {
        s_x[i] = pos[i * 3 + 0];
        s_y[i] = pos[i * 3 + 1];
        s_z[i] = pos[i * 3 + 2];
    }
    // 2*NSLOT == 256 == TFPS: each thread zeroes exactly one slot
    s_mbox[t >= NSLOT][t & (NSLOT - 1)] = 0ull;
    if (rank == 0 && t == 0) g_idx[0] = 0;
    __syncthreads();
    asm volatile("barrier.cluster.arrive.aligned;" ::: "memory");
    asm volatile("barrier.cluster.wait.aligned;"   ::: "memory");

    // precomputed addresses
    const unsigned a_slot_local = smem_u32(&s_mbox[0][rank * NW + w]);
    const unsigned a_poll       = smem_u32(&s_mbox[0][lane * 4]);   // 4 contiguous slots
    unsigned a_remote = 0;
    if (lane < CLS) {
        asm("mapa.shared::cluster.u32 %0, %1, %2;"
            : "=r"(a_remote) : "r"(a_slot_local), "r"(lane));
    }

    // this thread's PPT points: gi = base + t + j*TFPS (ascending in j)
    const int base = (int)rank * (TFPS * PPT) + t;
    float px[PPT], py[PPT], pz[PPT], dmin[PPT];
    #pragma unroll
    for (int j = 0; j < PPT; ++j) {
        int gi = base + j * TFPS;
        px[j] = s_x[gi]; py[j] = s_y[gi]; pz[j] = s_z[gi];
        dmin[j] = CUDART_INF_F;
    }
    float cx = s_x[0], cy = s_y[0], cz = s_z[0];

    for (int it = 1; it < MCTR; ++it) {
        const unsigned poff = (it & 1) ? (unsigned)(NSLOT * 8) : 0u;

        // exact reference arithmetic: ((dx*dx + dy*dy) + dz*dz), all rn, no FMA
        // thread-local argmax with first-index tie-break (ascending gi, strict >)
        float bestv = -1.0f;
        int   bestj = 0;
        #pragma unroll
        for (int j = 0; j < PPT; ++j) {
            float dx = px[j] - cx, dy = py[j] - cy, dz = pz[j] - cz;
            float d = __fadd_rn(__fadd_rn(__fmul_rn(dx, dx), __fmul_rn(dy, dy)),
                                __fmul_rn(dz, dz));
            float dm = fminf(dmin[j], d);
            dmin[j] = dm;
            if (dm > bestv) { bestv = dm; bestj = j; }
        }
        int besti = base + bestj * TFPS;

        // warp argmax: max value (nonneg float bits monotone as u32), then min index
        unsigned vb   = __float_as_uint(bestv);
        unsigned wmax = __reduce_max_sync(0xffffffffu, vb);
        int cand = (vb == wmax) ? besti : 0x7fffffff;
        int wi   = __reduce_min_sync(0xffffffffu, cand);
        unsigned long long wkey =
            ((unsigned long long)wmax << 32)
          | ((unsigned long long)(0x3FFFu - (unsigned)wi) << 12)
          | (unsigned)it;

        // push this warp's key to its slot in EVERY CTA (16 lanes, 1 instr)
        if (lane < CLS) {
            asm volatile("st.relaxed.cluster.shared::cluster.b64 [%0], %1;"
                         :: "r"(a_remote + poff), "l"(wkey) : "memory");
        }

        // poll 4 contiguous local slots per lane via two vector LDS
        unsigned long long k0, k1, k2, k3;
        const unsigned pa = a_poll + poff;
        for (;;) {
            asm volatile("ld.volatile.shared.v2.u64 {%0, %1}, [%2];"
                         : "=l"(k0), "=l"(k1) : "r"(pa) : "memory");
            asm volatile("ld.volatile.shared.v2.u64 {%0, %1}, [%2];"
                         : "=l"(k2), "=l"(k3) : "r"(pa + 16) : "memory");
            bool ok = ((unsigned)(k0 & 0xFFFu) == (unsigned)it)
                   && ((unsigned)(k1 & 0xFFFu) == (unsigned)it)
                   && ((unsigned)(k2 & 0xFFFu) == (unsigned)it)
                   && ((unsigned)(k3 & 0xFFFu) == (unsigned)it);
            if (__all_sync(0xffffffffu, ok)) break;
        }
        unsigned long long ka = (k0 > k1) ? k0 : k1;
        unsigned long long kb = (k2 > k3) ? k2 : k3;
        unsigned long long k  = (ka > kb) ? ka : kb;  // same tag -> pure key order
        unsigned hi   = (unsigned)(k >> 32);
        unsigned gmax = __reduce_max_sync(0xffffffffu, hi);
        unsigned lo   = (hi == gmax) ? (unsigned)k : 0u;
        unsigned glo  = __reduce_max_sync(0xffffffffu, lo);
        int gidx = (int)(0x3FFFu - ((glo >> 12) & 0x3FFFu));

        if (rank == 0 && w == 0 && lane == 0) g_idx[it] = gidx;  // fire-and-forget

        cx = s_x[gidx]; cy = s_y[gidx]; cz = s_z[gidx];          // broadcast LDS
    }

    // no CTA may exit while peers could still target its smem
    asm volatile("barrier.cluster.arrive.aligned;" ::: "memory");
    asm volatile("barrier.cluster.wait.aligned;"   ::: "memory");
}

// ---------------- Stage 2: ball query ----------------
#define CHUNK 2048
__global__ __launch_bounds__(256)
void nbr_kernel(const float* __restrict__ pos)
{
    __shared__ float sx[CHUNK], sy[CHUNK], sz[CHUNK];
    __shared__ int   s_ci[8][MAXC];
    __shared__ float s_cd[8][MAXC];

    const int tid  = threadIdx.x;
    const int w    = tid >> 5;
    const int lane = tid & 31;
    const int m    = blockIdx.x * 8 + w;

    const int cidx = g_idx[m];
    const float cx = pos[cidx * 3 + 0];
    const float cy = pos[cidx * 3 + 1];
    const float cz = pos[cidx * 3 + 2];

    int cnt = 0;
    for (int base = 0; base < NPTS; base += CHUNK) {
        __syncthreads();
        for (int i = tid; i < CHUNK; i += 256) {
            sx[i] = pos[(base + i) * 3 + 0];
            sy[i] = pos[(base + i) * 3 + 1];
            sz[i] = pos[(base + i) * 3 + 2];
        }
        __syncthreads();
        for (int i = lane; i < CHUNK; i += 32) {
            float dx = sx[i] - cx, dy = sy[i] - cy, dz = sz[i] - cz;
            float d2 = __fadd_rn(__fadd_rn(__fmul_rn(dx, dx), __fmul_rn(dy, dy)),
                                 __fmul_rn(dz, dz));
            bool in = (d2 <= RAD2);
            unsigned mk = __ballot_sync(0xffffffffu, in);
            int slot = cnt + __popc(mk & ((1u << lane) - 1u));
            if (in && slot < MAXC) { s_ci[w][slot] = base + i; s_cd[w][slot] = d2; }
            cnt += __popc(mk);
        }
    }
    cnt = min(cnt, MAXC);

    if (cnt <= KNBR) {
        if (lane < cnt) g_nbr[m * KNBR + lane] = s_ci[w][lane];
        if (lane == 0)  g_cnt[m] = cnt;
    } else {
        for (int c = lane; c < cnt; c += 32) {
            float d = s_cd[w][c];
            int  ii = s_ci[w][c];
            int r = 0;
            for (int o = 0; o < cnt; ++o) {
                float d2o = s_cd[w][o];
                r += (d2o < d) || (d2o == d && s_ci[w][o] < ii);
            }
            if (r < KNBR) g_nbr[m * KNBR + r] = ii;
        }
        if (lane == 0) g_cnt[m] = KNBR;
    }
}

// ---------------- Stage 3: per-edge MLP + masked max aggregation ----------------
__global__ __launch_bounds__(256)
void mlp_kernel(const float* __restrict__ feat,
                const float* __restrict__ pos,
                const float* __restrict__ W1, const float* __restrict__ b1,
                const float* __restrict__ W2, const float* __restrict__ b2,
                const float* __restrict__ W3, const float* __restrict__ b3,
                float* __restrict__ out)
{
    __shared__ float xb[32][68];
    __shared__ float h1[32][64];
    __shared__ float h2[32][64];
    __shared__ float h3[32][128];

    const int m    = blockIdx.x;
    const int tid  = threadIdx.x;
    const int w    = tid >> 5;
    const int lane = tid & 31;
    const int cnt  = g_cnt[m];

    const int cidx = g_idx[m];
    const float cx = pos[cidx * 3 + 0];
    const float cy = pos[cidx * 3 + 1];
    const float cz = pos[cidx * 3 + 2];

    for (int k = w; k < cnt; k += 8) {
        int j = g_nbr[m * KNBR + k];
        xb[k][lane]      = feat[j * FIN + lane];
        xb[k][lane + 32] = feat[j * FIN + lane + 32];
        if (lane == 0) {
            xb[k][64] = pos[j * 3 + 0] - cx;
            xb[k][65] = pos[j * 3 + 1] - cy;
            xb[k][66] = pos[j * 3 + 2] - cz;
        }
    }
    __syncthreads();

    for (int p = tid; p < cnt * 64; p += 256) {
        int k = p >> 6, o = p & 63;
        float acc = b1[o];
        #pragma unroll
        for (int i = 0; i < 67; ++i)
            acc = fmaf(xb[k][i], W1[i * 64 + o], acc);
        h1[k][o] = fmaxf(acc, 0.0f);
    }
    __syncthreads();

    for (int p = tid; p < cnt * 64; p += 256) {
        int k = p >> 6, o = p & 63;
        float acc = b2[o];
        #pragma unroll
        for (int i = 0; i < 64; ++i)
            acc = fmaf(h1[k][i], W2[i * 64 + o], acc);
        h2[k][o] = fmaxf(acc, 0.0f);
    }
    __syncthreads();

    for (int p = tid; p < cnt * 128; p += 256) {
        int k = p >> 7, o = p & 127;
        float acc = b3[o];
        #pragma unroll
        for (int i = 0; i < 64; ++i)
            acc = fmaf(h2[k][i], W3[i * 128 + o], acc);
        h3[k][o] = fmaxf(acc, 0.0f);
    }
    __syncthreads();

    if (tid < 128) {
        float mx = -CUDART_INF_F;
        for (int k = 0; k < cnt; ++k) mx = fmaxf(mx, h3[k][tid]);
        out[m * 128 + tid] = mx;
    }
}

// ---------------- Stage 4: tail outputs ----------------
__global__ void tail_kernel(const float* __restrict__ pos, float* __restrict__ out,
                            int out_size)
{
    int m = blockIdx.x * blockDim.x + threadIdx.x;
    if (m >= MCTR) return;
    const int base = MCTR * 128;
    if (out_size >= base + 3 * MCTR) {
        int j = g_idx[m];
        out[base + 3 * m + 0] = pos[3 * j + 0];
        out[base + 3 * m + 1] = pos[3 * j + 1];
        out[base + 3 * m + 2] = pos[3 * j + 2];
    }
    if (out_size >= base + 3 * MCTR + MCTR) {
        out[base + 3 * MCTR + m] = 0.0f;
    }
}

extern "C" void kernel_launch(void* const* d_in, const int* in_sizes, int n_in,
                              void* d_out, int out_size)
{
    const float* feat = (const float*)d_in[0];
    const float* pos  = (const float*)d_in[1];
    const float* W1 = (const float*)d_in[3];
    const float* b1 = (const float*)d_in[4];
    const float* W2 = (const float*)d_in[5];
    const float* b2 = (const float*)d_in[6];
    const float* W3 = (const float*)d_in[7];
    const float* b3 = (const float*)d_in[8];
    float* out = (float*)d_out;

    const size_t fps_smem = 3 * NPTS * sizeof(float);   // 192KB
    cudaFuncSetAttribute(fps_kernel, cudaFuncAttributeMaxDynamicSharedMemorySize,
                         (int)fps_smem);
    cudaFuncSetAttribute(fps_kernel, cudaFuncAttributeNonPortableClusterSizeAllowed, 1);

    fps_kernel<<<CLS, TFPS, fps_smem>>>(pos);
    nbr_kernel<<<MCTR / 8, 256>>>(pos);
    mlp_kernel<<<MCTR, 256>>>(feat, pos, W1, b1, W2, b2, W3, b3, out);
    tail_kernel<<<(MCTR + 255) / 256, 256>>>(pos, out, out_size);
}

// round 11
// speedup vs baseline: 1.0884x; 1.0884x over previous
#include <cuda_runtime.h>
#include <cuda_bf16.h>
#include <math_constants.h>

#define NPTS 16384
#define MCTR 4096
#define KNBR 32
#define FIN  64
#define RAD2 0.25f
#define MAXC 64

#define CLS  8       // FPS cluster size (CTAs) — 8 is the proven sweet spot
#define TFPS 512     // threads per FPS CTA
#define PPT  4       // points per thread; CLS*TFPS*PPT == NPTS
#define NW   (TFPS / 32)
#define NSLOT (CLS * NW)   // 128 warp-key slots per parity

// ---------------- device scratch (no allocations allowed) ----------------
__device__ int g_idx[MCTR];
__device__ int g_nbr[MCTR * KNBR];
__device__ int g_cnt[MCTR];

__device__ __forceinline__ unsigned smem_u32(const void* p)
{
    unsigned a;
    asm("{ .reg .u64 t; cvta.to.shared.u64 t, %1; cvt.u32.u64 %0, t; }"
        : "=r"(a) : "l"(p));
    return a;
}

// ---------------- Stage 1: cluster-cooperative FPS, direct warp-key exchange ----------------
// key = bits(val)<<32 | (0x3FFF - idx)<<12 | tag(12 bits = iteration)
// All warps symmetric: warp-REDUX -> push warp key to all 8 CTAs -> poll 128
// local slots (4 contiguous per lane, vector LDS) -> reduce -> center lookup.
__global__ __launch_bounds__(TFPS, 1) __cluster_dims__(CLS, 1, 1)
void fps_kernel(const float* __restrict__ pos)
{
    extern __shared__ float s_tab[];
    float* s_x = s_tab;
    float* s_y = s_tab + NPTS;
    float* s_z = s_tab + 2 * NPTS;

    __shared__ unsigned long long s_mbox[2][NSLOT];  // [parity][srcCTA*NW + srcWarp]

    const int t    = threadIdx.x;
    const int w    = t >> 5;
    const int lane = t & 31;
    unsigned rank;
    asm("mov.u32 %0, %%cluster_ctarank;" : "=r"(rank));

    // one-time: local coordinate table + mailbox init
    for (int i = t; i < NPTS; i += TFPS) {
        s_x[i] = pos[i * 3 + 0];
        s_y[i] = pos[i * 3 + 1];
        s_z[i] = pos[i * 3 + 2];
    }
    if (t < 2 * NSLOT) s_mbox[t >= NSLOT][t & (NSLOT - 1)] = 0ull;
    if (rank == 0 && t == 0) g_idx[0] = 0;
    __syncthreads();
    asm volatile("barrier.cluster.arrive.aligned;" ::: "memory");
    asm volatile("barrier.cluster.wait.aligned;"   ::: "memory");

    // precomputed addresses
    const unsigned a_slot_local = smem_u32(&s_mbox[0][rank * NW + w]);
    const unsigned a_poll       = smem_u32(&s_mbox[0][lane * 4]);   // 4 contiguous slots
    unsigned a_remote = 0;
    if (lane < CLS) {
        asm("mapa.shared::cluster.u32 %0, %1, %2;"
            : "=r"(a_remote) : "r"(a_slot_local), "r"(lane));
    }

    // this thread's PPT points: gi = base + t + j*TFPS (ascending in j)
    const int base = (int)rank * (TFPS * PPT) + t;
    float px[PPT], py[PPT], pz[PPT], dmin[PPT];
    #pragma unroll
    for (int j = 0; j < PPT; ++j) {
        int gi = base + j * TFPS;
        px[j] = s_x[gi]; py[j] = s_y[gi]; pz[j] = s_z[gi];
        dmin[j] = CUDART_INF_F;
    }
    float cx = s_x[0], cy = s_y[0], cz = s_z[0];

    for (int it = 1; it < MCTR; ++it) {
        const unsigned poff = (it & 1) ? (unsigned)(NSLOT * 8) : 0u;

        // exact reference arithmetic: ((dx*dx + dy*dy) + dz*dz), all rn, no FMA
        // thread-local argmax with first-index tie-break (ascending gi, strict >)
        float bestv = -1.0f;
        int   bestj = 0;
        #pragma unroll
        for (int j = 0; j < PPT; ++j) {
            float dx = px[j] - cx, dy = py[j] - cy, dz = pz[j] - cz;
            float d = __fadd_rn(__fadd_rn(__fmul_rn(dx, dx), __fmul_rn(dy, dy)),
                                __fmul_rn(dz, dz));
            float dm = fminf(dmin[j], d);
            dmin[j] = dm;
            if (dm > bestv) { bestv = dm; bestj = j; }
        }
        int besti = base + bestj * TFPS;

        // warp argmax: max value (nonneg float bits monotone as u32), then min index
        unsigned vb   = __float_as_uint(bestv);
        unsigned wmax = __reduce_max_sync(0xffffffffu, vb);
        int cand = (vb == wmax) ? besti : 0x7fffffff;
        int wi   = __reduce_min_sync(0xffffffffu, cand);
        unsigned long long wkey =
            ((unsigned long long)wmax << 32)
          | ((unsigned long long)(0x3FFFu - (unsigned)wi) << 12)
          | (unsigned)it;

        // push this warp's key to its slot in EVERY CTA (8 lanes, 1 instr)
        if (lane < CLS) {
            asm volatile("st.relaxed.cluster.shared::cluster.b64 [%0], %1;"
                         :: "r"(a_remote + poff), "l"(wkey) : "memory");
        }

        // poll 4 contiguous local slots per lane via two vector LDS
        unsigned long long k0, k1, k2, k3;
        const unsigned pa = a_poll + poff;
        for (;;) {
            asm volatile("ld.volatile.shared.v2.u64 {%0, %1}, [%2];"
                         : "=l"(k0), "=l"(k1) : "r"(pa) : "memory");
            asm volatile("ld.volatile.shared.v2.u64 {%0, %1}, [%2];"
                         : "=l"(k2), "=l"(k3) : "r"(pa + 16) : "memory");
            bool ok = ((unsigned)(k0 & 0xFFFu) == (unsigned)it)
                   && ((unsigned)(k1 & 0xFFFu) == (unsigned)it)
                   && ((unsigned)(k2 & 0xFFFu) == (unsigned)it)
                   && ((unsigned)(k3 & 0xFFFu) == (unsigned)it);
            if (__all_sync(0xffffffffu, ok)) break;
        }
        unsigned long long ka = (k0 > k1) ? k0 : k1;
        unsigned long long kb = (k2 > k3) ? k2 : k3;
        unsigned long long k  = (ka > kb) ? ka : kb;  // same tag -> pure key order
        unsigned hi   = (unsigned)(k >> 32);
        unsigned gmax = __reduce_max_sync(0xffffffffu, hi);
        unsigned lo   = (hi == gmax) ? (unsigned)k : 0u;
        unsigned glo  = __reduce_max_sync(0xffffffffu, lo);
        int gidx = (int)(0x3FFFu - ((glo >> 12) & 0x3FFFu));

        if (rank == 0 && w == 0 && lane == 0) g_idx[it] = gidx;  // fire-and-forget

        cx = s_x[gidx]; cy = s_y[gidx]; cz = s_z[gidx];          // broadcast LDS
    }

    // no CTA may exit while peers could still target its smem
    asm volatile("barrier.cluster.arrive.aligned;" ::: "memory");
    asm volatile("barrier.cluster.wait.aligned;"   ::: "memory");
}

// ---------------- Stage 2: ball query ----------------
#define CHUNK 2048
__global__ __launch_bounds__(256)
void nbr_kernel(const float* __restrict__ pos)
{
    __shared__ float sx[CHUNK], sy[CHUNK], sz[CHUNK];
    __shared__ int   s_ci[8][MAXC];
    __shared__ float s_cd[8][MAXC];

    const int tid  = threadIdx.x;
    const int w    = tid >> 5;
    const int lane = tid & 31;
    const int m    = blockIdx.x * 8 + w;

    const int cidx = g_idx[m];
    const float cx = pos[cidx * 3 + 0];
    const float cy = pos[cidx * 3 + 1];
    const float cz = pos[cidx * 3 + 2];

    int cnt = 0;
    for (int base = 0; base < NPTS; base += CHUNK) {
        __syncthreads();
        for (int i = tid; i < CHUNK; i += 256) {
            sx[i] = pos[(base + i) * 3 + 0];
            sy[i] = pos[(base + i) * 3 + 1];
            sz[i] = pos[(base + i) * 3 + 2];
        }
        __syncthreads();
        for (int i = lane; i < CHUNK; i += 32) {
            float dx = sx[i] - cx, dy = sy[i] - cy, dz = sz[i] - cz;
            float d2 = __fadd_rn(__fadd_rn(__fmul_rn(dx, dx), __fmul_rn(dy, dy)),
                                 __fmul_rn(dz, dz));
            bool in = (d2 <= RAD2);
            unsigned mk = __ballot_sync(0xffffffffu, in);
            int slot = cnt + __popc(mk & ((1u << lane) - 1u));
            if (in && slot < MAXC) { s_ci[w][slot] = base + i; s_cd[w][slot] = d2; }
            cnt += __popc(mk);
        }
    }
    cnt = min(cnt, MAXC);

    if (cnt <= KNBR) {
        if (lane < cnt) g_nbr[m * KNBR + lane] = s_ci[w][lane];
        if (lane == 0)  g_cnt[m] = cnt;
    } else {
        for (int c = lane; c < cnt; c += 32) {
            float d = s_cd[w][c];
            int  ii = s_ci[w][c];
            int r = 0;
            for (int o = 0; o < cnt; ++o) {
                float d2o = s_cd[w][o];
                r += (d2o < d) || (d2o == d && s_ci[w][o] < ii);
            }
            if (r < KNBR) g_nbr[m * KNBR + r] = ii;
        }
        if (lane == 0) g_cnt[m] = KNBR;
    }
}

// ---------------- Stage 3: per-edge MLP + masked max aggregation ----------------
__global__ __launch_bounds__(256)
void mlp_kernel(const float* __restrict__ feat,
                const float* __restrict__ pos,
                const float* __restrict__ W1, const float* __restrict__ b1,
                const float* __restrict__ W2, const float* __restrict__ b2,
                const float* __restrict__ W3, const float* __restrict__ b3,
                float* __restrict__ out)
{
    __shared__ float xb[32][68];
    __shared__ float h1[32][64];
    __shared__ float h2[32][64];
    __shared__ float h3[32][128];

    const int m    = blockIdx.x;
    const int tid  = threadIdx.x;
    const int w    = tid >> 5;
    const int lane = tid & 31;
    const int cnt  = g_cnt[m];

    const int cidx = g_idx[m];
    const float cx = pos[cidx * 3 + 0];
    const float cy = pos[cidx * 3 + 1];
    const float cz = pos[cidx * 3 + 2];

    for (int k = w; k < cnt; k += 8) {
        int j = g_nbr[m * KNBR + k];
        xb[k][lane]      = feat[j * FIN + lane];
        xb[k][lane + 32] = feat[j * FIN + lane + 32];
        if (lane == 0) {
            xb[k][64] = pos[j * 3 + 0] - cx;
            xb[k][65] = pos[j * 3 + 1] - cy;
            xb[k][66] = pos[j * 3 + 2] - cz;
        }
    }
    __syncthreads();

    for (int p = tid; p < cnt * 64; p += 256) {
        int k = p >> 6, o = p & 63;
        float acc = b1[o];
        #pragma unroll
        for (int i = 0; i < 67; ++i)
            acc = fmaf(xb[k][i], W1[i * 64 + o], acc);
        h1[k][o] = fmaxf(acc, 0.0f);
    }
    __syncthreads();

    for (int p = tid; p < cnt * 64; p += 256) {
        int k = p >> 6, o = p & 63;
        float acc = b2[o];
        #pragma unroll
        for (int i = 0; i < 64; ++i)
            acc = fmaf(h1[k][i], W2[i * 64 + o], acc);
        h2[k][o] = fmaxf(acc, 0.0f);
    }
    __syncthreads();

    for (int p = tid; p < cnt * 128; p += 256) {
        int k = p >> 7, o = p & 127;
        float acc = b3[o];
        #pragma unroll
        for (int i = 0; i < 64; ++i)
            acc = fmaf(h2[k][i], W3[i * 128 + o], acc);
        h3[k][o] = fmaxf(acc, 0.0f);
    }
    __syncthreads();

    if (tid < 128) {
        float mx = -CUDART_INF_F;
        for (int k = 0; k < cnt; ++k) mx = fmaxf(mx, h3[k][tid]);
        out[m * 128 + tid] = mx;
    }
}

// ---------------- Stage 4: tail outputs ----------------
__global__ void tail_kernel(const float* __restrict__ pos, float* __restrict__ out,
                            int out_size)
{
    int m = blockIdx.x * blockDim.x + threadIdx.x;
    if (m >= MCTR) return;
    const int base = MCTR * 128;
    if (out_size >= base + 3 * MCTR) {
        int j = g_idx[m];
        out[base + 3 * m + 0] = pos[3 * j + 0];
        out[base + 3 * m + 1] = pos[3 * j + 1];
        out[base + 3 * m + 2] = pos[3 * j + 2];
    }
    if (out_size >= base + 3 * MCTR + MCTR) {
        out[base + 3 * MCTR + m] = 0.0f;
    }
}

extern "C" void kernel_launch(void* const* d_in, const int* in_sizes, int n_in,
                              void* d_out, int out_size)
{
    const float* feat = (const float*)d_in[0];
    const float* pos  = (const float*)d_in[1];
    const float* W1 = (const float*)d_in[3];
    const float* b1 = (const float*)d_in[4];
    const float* W2 = (const float*)d_in[5];
    const float* b2 = (const float*)d_in[6];
    const float* W3 = (const float*)d_in[7];
    const float* b3 = (const float*)d_in[8];
    float* out = (float*)d_out;

    const size_t fps_smem = 3 * NPTS * sizeof(float);   // 192KB
    cudaFuncSetAttribute(fps_kernel, cudaFuncAttributeMaxDynamicSharedMemorySize,
                         (int)fps_smem);

    fps_kernel<<<CLS, TFPS, fps_smem>>>(pos);
    nbr_kernel<<<MCTR / 8, 256>>>(pos);
    mlp_kernel<<<MCTR, 256>>>(feat, pos, W1, b1, W2, b2, W3, b3, out);
    tail_kernel<<<(MCTR + 255) / 256, 256>>>(pos, out, out_size);
}

// round 12
// speedup vs baseline: 1.7941x; 1.6483x over previous
#include <cuda_runtime.h>
#include <cuda_bf16.h>
#include <math_constants.h>

#define NPTS 16384
#define MCTR 4096
#define KNBR 32
#define FIN  64
#define RAD2 0.25f
#define MAXC 64

#define CLS  8       // FPS cluster size (CTAs) — proven sweet spot
#define TFPS 256     // threads per FPS CTA — proven sweet spot
#define PPT  8       // points per thread; CLS*TFPS*PPT == NPTS
#define NPAIR (PPT / 2)
#define NW   (TFPS / 32)
#define NSLOT (CLS * NW)   // 64 warp-key slots per parity (proven message count)

// ---------------- device scratch (no allocations allowed) ----------------
__device__ int g_idx[MCTR];
__device__ int g_nbr[MCTR * KNBR];
__device__ int g_cnt[MCTR];

__device__ __forceinline__ unsigned smem_u32(const void* p)
{
    unsigned a;
    asm("{ .reg .u64 t; cvta.to.shared.u64 t, %1; cvt.u32.u64 %0, t; }"
        : "=r"(a) : "l"(p));
    return a;
}
__device__ __forceinline__ unsigned long long lds_vol_u64(unsigned a)
{
    unsigned long long v;
    asm volatile("ld.volatile.shared.b64 %0, [%1];" : "=l"(v) : "r"(a) : "memory");
    return v;
}

#define PACK_F32X2(out, lo, hi) \
    asm("mov.b64 %0, {%1, %2};" : "=l"(out) : "f"(lo), "f"(hi))
#define UNPACK_F32X2(lo, hi, in) \
    asm("mov.b64 {%0, %1}, %2;" : "=f"(lo), "=f"(hi) : "l"(in))
#define ADD_X2(out, a, b) \
    asm("add.rn.f32x2 %0, %1, %2;" : "=l"(out) : "l"(a), "l"(b))
#define MUL_X2(out, a, b) \
    asm("mul.rn.f32x2 %0, %1, %2;" : "=l"(out) : "l"(a), "l"(b))

// ---------------- Stage 1: cluster-cooperative FPS, direct warp-key exchange ----------------
// key = bits(val)<<32 | (0x3FFF - idx)<<12 | tag(12 bits = iteration)
// All warps symmetric: packed-f32x2 distance update -> warp-REDUX -> push warp
// key to all 8 CTAs -> poll 64 local slots -> reduce -> center lookup.
__global__ __launch_bounds__(TFPS, 1) __cluster_dims__(CLS, 1, 1)
void fps_kernel(const float* __restrict__ pos)
{
    extern __shared__ float s_tab[];
    float* s_x = s_tab;
    float* s_y = s_tab + NPTS;
    float* s_z = s_tab + 2 * NPTS;

    __shared__ unsigned long long s_mbox[2][NSLOT];  // [parity][srcCTA*NW + srcWarp]

    const int t    = threadIdx.x;
    const int w    = t >> 5;
    const int lane = t & 31;
    unsigned rank;
    asm("mov.u32 %0, %%cluster_ctarank;" : "=r"(rank));

    // one-time: local coordinate table + mailbox init
    for (int i = t; i < NPTS; i += TFPS) {
        s_x[i] = pos[i * 3 + 0];
        s_y[i] = pos[i * 3 + 1];
        s_z[i] = pos[i * 3 + 2];
    }
    if (t < 2 * NSLOT) s_mbox[t >= NSLOT][t & (NSLOT - 1)] = 0ull;
    if (rank == 0 && t == 0) g_idx[0] = 0;
    __syncthreads();
    asm volatile("barrier.cluster.arrive.aligned;" ::: "memory");
    asm volatile("barrier.cluster.wait.aligned;"   ::: "memory");

    // precomputed addresses (R9 layout: 2 scalar polls at lane, lane+32)
    const unsigned a_slot_local = smem_u32(&s_mbox[0][rank * NW + w]);
    const unsigned a_poll0      = smem_u32(&s_mbox[0][lane]);
    const unsigned a_poll1      = smem_u32(&s_mbox[0][lane + 32]);
    unsigned a_remote = 0;
    if (lane < CLS) {
        asm("mapa.shared::cluster.u32 %0, %1, %2;"
            : "=r"(a_remote) : "r"(a_slot_local), "r"(lane));
    }

    // this thread's points, packed in pairs: pair j = points (2j, 2j+1),
    // gi = base + k*TFPS ascending in k — preserves first-index tie-break.
    const int base = (int)rank * (TFPS * PPT) + t;
    unsigned long long px2[NPAIR], py2[NPAIR], pz2[NPAIR];
    float dmin[PPT];
    #pragma unroll
    for (int j = 0; j < NPAIR; ++j) {
        int glo = base + (2 * j) * TFPS;
        int ghi = glo + TFPS;
        PACK_F32X2(px2[j], s_x[glo], s_x[ghi]);
        PACK_F32X2(py2[j], s_y[glo], s_y[ghi]);
        PACK_F32X2(pz2[j], s_z[glo], s_z[ghi]);
        dmin[2 * j] = CUDART_INF_F;
        dmin[2 * j + 1] = CUDART_INF_F;
    }
    float cx = s_x[0], cy = s_y[0], cz = s_z[0];

    for (int it = 1; it < MCTR; ++it) {
        const unsigned poff = (it & 1) ? (unsigned)(NSLOT * 8) : 0u;

        // packed negated center (x - c == x + (-c), exact)
        float ncx = -cx, ncy = -cy, ncz = -cz;
        unsigned long long ncx2, ncy2, ncz2;
        PACK_F32X2(ncx2, ncx, ncx);
        PACK_F32X2(ncy2, ncy, ncy);
        PACK_F32X2(ncz2, ncz, ncz);

        // exact reference arithmetic per lane-pair: ((dx*dx + dy*dy) + dz*dz),
        // all rn, no FMA; argmax with first-index tie-break (strict >)
        float bestv = -1.0f;
        int   bestk = 0;
        #pragma unroll
        for (int j = 0; j < NPAIR; ++j) {
            unsigned long long dx2, dy2, dz2, xx, yy, zz, s2, d2;
            ADD_X2(dx2, px2[j], ncx2);
            ADD_X2(dy2, py2[j], ncy2);
            ADD_X2(dz2, pz2[j], ncz2);
            MUL_X2(xx, dx2, dx2);
            MUL_X2(yy, dy2, dy2);
            MUL_X2(zz, dz2, dz2);
            ADD_X2(s2, xx, yy);
            ADD_X2(d2, s2, zz);
            float dlo, dhi;
            UNPACK_F32X2(dlo, dhi, d2);
            float m0 = fminf(dmin[2 * j], dlo);
            dmin[2 * j] = m0;
            if (m0 > bestv) { bestv = m0; bestk = 2 * j; }
            float m1 = fminf(dmin[2 * j + 1], dhi);
            dmin[2 * j + 1] = m1;
            if (m1 > bestv) { bestv = m1; bestk = 2 * j + 1; }
        }
        int besti = base + bestk * TFPS;

        // warp argmax: max value (nonneg float bits monotone as u32), then min index
        unsigned vb   = __float_as_uint(bestv);
        unsigned wmax = __reduce_max_sync(0xffffffffu, vb);
        int cand = (vb == wmax) ? besti : 0x7fffffff;
        int wi   = __reduce_min_sync(0xffffffffu, cand);
        unsigned long long wkey =
            ((unsigned long long)wmax << 32)
          | ((unsigned long long)(0x3FFFu - (unsigned)wi) << 12)
          | (unsigned)it;

        // push this warp's key to its slot in EVERY CTA (8 lanes, 1 instr)
        if (lane < CLS) {
            asm volatile("st.relaxed.cluster.shared::cluster.b64 [%0], %1;"
                         :: "r"(a_remote + poff), "l"(wkey) : "memory");
        }

        // poll all 64 local slots (2 per lane); u64-max fold then hi/lo REDUX
        unsigned long long k0, k1;
        for (;;) {
            k0 = lds_vol_u64(a_poll0 + poff);
            k1 = lds_vol_u64(a_poll1 + poff);
            bool ok = ((unsigned)(k0 & 0xFFFu) == (unsigned)it)
                   && ((unsigned)(k1 & 0xFFFu) == (unsigned)it);
            if (__all_sync(0xffffffffu, ok)) break;
        }
        unsigned long long k = (k0 > k1) ? k0 : k1;   // same tag -> pure key order
        unsigned hi   = (unsigned)(k >> 32);
        unsigned gmax = __reduce_max_sync(0xffffffffu, hi);
        unsigned lo   = (hi == gmax) ? (unsigned)k : 0u;
        unsigned glo  = __reduce_max_sync(0xffffffffu, lo);
        int gidx = (int)(0x3FFFu - ((glo >> 12) & 0x3FFFu));

        if (rank == 0 && w == 0 && lane == 0) g_idx[it] = gidx;  // fire-and-forget

        cx = s_x[gidx]; cy = s_y[gidx]; cz = s_z[gidx];          // broadcast LDS
    }

    // no CTA may exit while peers could still target its smem
    asm volatile("barrier.cluster.arrive.aligned;" ::: "memory");
    asm volatile("barrier.cluster.wait.aligned;"   ::: "memory");
}

// ---------------- Stage 2: ball query ----------------
#define CHUNK 2048
__global__ __launch_bounds__(256)
void nbr_kernel(const float* __restrict__ pos)
{
    __shared__ float sx[CHUNK], sy[CHUNK], sz[CHUNK];
    __shared__ int   s_ci[8][MAXC];
    __shared__ float s_cd[8][MAXC];

    const int tid  = threadIdx.x;
    const int w    = tid >> 5;
    const int lane = tid & 31;
    const int m    = blockIdx.x * 8 + w;

    const int cidx = g_idx[m];
    const float cx = pos[cidx * 3 + 0];
    const float cy = pos[cidx * 3 + 1];
    const float cz = pos[cidx * 3 + 2];

    int cnt = 0;
    for (int base = 0; base < NPTS; base += CHUNK) {
        __syncthreads();
        for (int i = tid; i < CHUNK; i += 256) {
            sx[i] = pos[(base + i) * 3 + 0];
            sy[i] = pos[(base + i) * 3 + 1];
            sz[i] = pos[(base + i) * 3 + 2];
        }
        __syncthreads();
        for (int i = lane; i < CHUNK; i += 32) {
            float dx = sx[i] - cx, dy = sy[i] - cy, dz = sz[i] - cz;
            float d2 = __fadd_rn(__fadd_rn(__fmul_rn(dx, dx), __fmul_rn(dy, dy)),
                                 __fmul_rn(dz, dz));
            bool in = (d2 <= RAD2);
            unsigned mk = __ballot_sync(0xffffffffu, in);
            int slot = cnt + __popc(mk & ((1u << lane) - 1u));
            if (in && slot < MAXC) { s_ci[w][slot] = base + i; s_cd[w][slot] = d2; }
            cnt += __popc(mk);
        }
    }
    cnt = min(cnt, MAXC);

    if (cnt <= KNBR) {
        if (lane < cnt) g_nbr[m * KNBR + lane] = s_ci[w][lane];
        if (lane == 0)  g_cnt[m] = cnt;
    } else {
        for (int c = lane; c < cnt; c += 32) {
            float d = s_cd[w][c];
            int  ii = s_ci[w][c];
            int r = 0;
            for (int o = 0; o < cnt; ++o) {
                float d2o = s_cd[w][o];
                r += (d2o < d) || (d2o == d && s_ci[w][o] < ii);
            }
            if (r < KNBR) g_nbr[m * KNBR + r] = ii;
        }
        if (lane == 0) g_cnt[m] = KNBR;
    }
}

// ---------------- Stage 3: per-edge MLP + masked max aggregation ----------------
__global__ __launch_bounds__(256)
void mlp_kernel(const float* __restrict__ feat,
                const float* __restrict__ pos,
                const float* __restrict__ W1, const float* __restrict__ b1,
                const float* __restrict__ W2, const float* __restrict__ b2,
                const float* __restrict__ W3, const float* __restrict__ b3,
                float* __restrict__ out)
{
    __shared__ float xb[32][68];
    __shared__ float h1[32][64];
    __shared__ float h2[32][64];
    __shared__ float h3[32][128];

    const int m    = blockIdx.x;
    const int tid  = threadIdx.x;
    const int w    = tid >> 5;
    const int lane = tid & 31;
    const int cnt  = g_cnt[m];

    const int cidx = g_idx[m];
    const float cx = pos[cidx * 3 + 0];
    const float cy = pos[cidx * 3 + 1];
    const float cz = pos[cidx * 3 + 2];

    for (int k = w; k < cnt; k += 8) {
        int j = g_nbr[m * KNBR + k];
        xb[k][lane]      = feat[j * FIN + lane];
        xb[k][lane + 32] = feat[j * FIN + lane + 32];
        if (lane == 0) {
            xb[k][64] = pos[j * 3 + 0] - cx;
            xb[k][65] = pos[j * 3 + 1] - cy;
            xb[k][66] = pos[j * 3 + 2] - cz;
        }
    }
    __syncthreads();

    for (int p = tid; p < cnt * 64; p += 256) {
        int k = p >> 6, o = p & 63;
        float acc = b1[o];
        #pragma unroll
        for (int i = 0; i < 67; ++i)
            acc = fmaf(xb[k][i], W1[i * 64 + o], acc);
        h1[k][o] = fmaxf(acc, 0.0f);
    }
    __syncthreads();

    for (int p = tid; p < cnt * 64; p += 256) {
        int k = p >> 6, o = p & 63;
        float acc = b2[o];
        #pragma unroll
        for (int i = 0; i < 64; ++i)
            acc = fmaf(h1[k][i], W2[i * 64 + o], acc);
        h2[k][o] = fmaxf(acc, 0.0f);
    }
    __syncthreads();

    for (int p = tid; p < cnt * 128; p += 256) {
        int k = p >> 7, o = p & 127;
        float acc = b3[o];
        #pragma unroll
        for (int i = 0; i < 64; ++i)
            acc = fmaf(h2[k][i], W3[i * 128 + o], acc);
        h3[k][o] = fmaxf(acc, 0.0f);
    }
    __syncthreads();

    if (tid < 128) {
        float mx = -CUDART_INF_F;
        for (int k = 0; k < cnt; ++k) mx = fmaxf(mx, h3[k][tid]);
        out[m * 128 + tid] = mx;
    }
}

// ---------------- Stage 4: tail outputs ----------------
__global__ void tail_kernel(const float* __restrict__ pos, float* __restrict__ out,
                            int out_size)
{
    int m = blockIdx.x * blockDim.x + threadIdx.x;
    if (m >= MCTR) return;
    const int base = MCTR * 128;
    if (out_size >= base + 3 * MCTR) {
        int j = g_idx[m];
        out[base + 3 * m + 0] = pos[3 * j + 0];
        out[base + 3 * m + 1] = pos[3 * j + 1];
        out[base + 3 * m + 2] = pos[3 * j + 2];
    }
    if (out_size >= base + 3 * MCTR + MCTR) {
        out[base + 3 * MCTR + m] = 0.0f;
    }
}

extern "C" void kernel_launch(void* const* d_in, const int* in_sizes, int n_in,
                              void* d_out, int out_size)
{
    const float* feat = (const float*)d_in[0];
    const float* pos  = (const float*)d_in[1];
    const float* W1 = (const float*)d_in[3];
    const float* b1 = (const float*)d_in[4];
    const float* W2 = (const float*)d_in[5];
    const float* b2 = (const float*)d_in[6];
    const float* W3 = (const float*)d_in[7];
    const float* b3 = (const float*)d_in[8];
    float* out = (float*)d_out;

    const size_t fps_smem = 3 * NPTS * sizeof(float);   // 192KB
    cudaFuncSetAttribute(fps_kernel, cudaFuncAttributeMaxDynamicSharedMemorySize,
                         (int)fps_smem);

    fps_kernel<<<CLS, TFPS, fps_smem>>>(pos);
    nbr_kernel<<<MCTR / 8, 256>>>(pos);
    mlp_kernel<<<MCTR, 256>>>(feat, pos, W1, b1, W2, b2, W3, b3, out);
    tail_kernel<<<(MCTR + 255) / 256, 256>>>(pos, out, out_size);
}

// round 14
// speedup vs baseline: 1.8326x; 1.0215x over previous
#include <cuda_runtime.h>
#include <cuda_bf16.h>
#include <math_constants.h>

#define NPTS 16384
#define MCTR 4096
#define KNBR 32
#define FIN  64
#define RAD2 0.25f
#define MAXC 64

#define CLS  8       // FPS cluster size (CTAs)
#define TFPS 256     // threads per CTA (both roles)
#define PPT  8       // points per FPS thread
#define NPAIR (PPT / 2)
#define NW   (TFPS / 32)
#define NSLOT (CLS * NW)    // 64 warp-key slots per parity
#define NCONS 104           // consumer CTAs (13 clusters) — placement slack
#define GRID  (CLS + NCONS) // 112 = 14 clusters of 8 (capacity is 16-17)

// ---------------- device scratch (no allocations allowed) ----------------
__device__ int      g_idx[MCTR];
__device__ unsigned g_flag[MCTR];   // (epoch<<14) | idx ; epoch guards replays
__device__ unsigned g_epoch;

__global__ void epoch_kernel() { if (threadIdx.x == 0) g_epoch = g_epoch + 1; }

__device__ __forceinline__ unsigned smem_u32(const void* p)
{
    unsigned a;
    asm("{ .reg .u64 t; cvta.to.shared.u64 t, %1; cvt.u32.u64 %0, t; }"
        : "=r"(a) : "l"(p));
    return a;
}
__device__ __forceinline__ unsigned long long lds_vol_u64(unsigned a)
{
    unsigned long long v;
    asm volatile("ld.volatile.shared.b64 %0, [%1];" : "=l"(v) : "r"(a) : "memory");
    return v;
}
__device__ __forceinline__ unsigned ldg_vol_u32(const unsigned* p)
{
    unsigned v;
    asm volatile("ld.volatile.global.u32 %0, [%1];" : "=r"(v) : "l"(p) : "memory");
    return v;
}

#define PACK_F32X2(out, lo, hi) \
    asm("mov.b64 %0, {%1, %2};" : "=l"(out) : "f"(lo), "f"(hi))
#define UNPACK_F32X2(lo, hi, in) \
    asm("mov.b64 {%0, %1}, %2;" : "=f"(lo), "=f"(hi) : "l"(in))
#define ADD_X2(out, a, b) \
    asm("add.rn.f32x2 %0, %1, %2;" : "=l"(out) : "l"(a), "l"(b))
#define MUL_X2(out, a, b) \
    asm("mul.rn.f32x2 %0, %1, %2;" : "=l"(out) : "l"(a), "l"(b))

// ============ fused kernel: cluster 0 = FPS producer, rest = consumers ============
__global__ __launch_bounds__(TFPS, 1) __cluster_dims__(CLS, 1, 1)
void fused_kernel(const float* __restrict__ pos,
                  const float* __restrict__ feat,
                  const float* __restrict__ W1, const float* __restrict__ b1,
                  const float* __restrict__ W2, const float* __restrict__ b2,
                  const float* __restrict__ W3, const float* __restrict__ b3,
                  float* __restrict__ out)
{
    extern __shared__ float dsm[];
    __shared__ unsigned long long s_mbox[2][NSLOT];

    const int t    = threadIdx.x;
    const int w    = t >> 5;
    const int lane = t & 31;
    const unsigned eh = g_epoch << 14;

    if (blockIdx.x < CLS) {
        // ================= FPS producer (R12 chain, unchanged) =================
        float* s_x = dsm;
        float* s_y = dsm + NPTS;
        float* s_z = dsm + 2 * NPTS;
        unsigned rank;
        asm("mov.u32 %0, %%cluster_ctarank;" : "=r"(rank));

        for (int i = t; i < NPTS; i += TFPS) {
            s_x[i] = pos[i * 3 + 0];
            s_y[i] = pos[i * 3 + 1];
            s_z[i] = pos[i * 3 + 2];
        }
        if (t < 2 * NSLOT) s_mbox[t >= NSLOT][t & (NSLOT - 1)] = 0ull;
        if (rank == 0 && t == 0) {
            g_idx[0] = 0;
            asm volatile("st.relaxed.gpu.global.u32 [%0], %1;"
                         :: "l"(&g_flag[0]), "r"(eh) : "memory");
        }
        __syncthreads();
        asm volatile("barrier.cluster.arrive.aligned;" ::: "memory");
        asm volatile("barrier.cluster.wait.aligned;"   ::: "memory");

        const unsigned a_slot_local = smem_u32(&s_mbox[0][rank * NW + w]);
        const unsigned a_poll0      = smem_u32(&s_mbox[0][lane]);
        const unsigned a_poll1      = smem_u32(&s_mbox[0][lane + 32]);
        unsigned a_remote = 0;
        if (lane < CLS) {
            asm("mapa.shared::cluster.u32 %0, %1, %2;"
                : "=r"(a_remote) : "r"(a_slot_local), "r"(lane));
        }

        const int base = (int)rank * (TFPS * PPT) + t;
        unsigned long long px2[NPAIR], py2[NPAIR], pz2[NPAIR];
        float dmin[PPT];
        #pragma unroll
        for (int j = 0; j < NPAIR; ++j) {
            int glo = base + (2 * j) * TFPS;
            int ghi = glo + TFPS;
            PACK_F32X2(px2[j], s_x[glo], s_x[ghi]);
            PACK_F32X2(py2[j], s_y[glo], s_y[ghi]);
            PACK_F32X2(pz2[j], s_z[glo], s_z[ghi]);
            dmin[2 * j] = CUDART_INF_F;
            dmin[2 * j + 1] = CUDART_INF_F;
        }
        float cx = s_x[0], cy = s_y[0], cz = s_z[0];

        for (int it = 1; it < MCTR; ++it) {
            const unsigned poff = (it & 1) ? (unsigned)(NSLOT * 8) : 0u;

            float ncx = -cx, ncy = -cy, ncz = -cz;
            unsigned long long ncx2, ncy2, ncz2;
            PACK_F32X2(ncx2, ncx, ncx);
            PACK_F32X2(ncy2, ncy, ncy);
            PACK_F32X2(ncz2, ncz, ncz);

            float bestv = -1.0f;
            int   bestk = 0;
            #pragma unroll
            for (int j = 0; j < NPAIR; ++j) {
                unsigned long long dx2, dy2, dz2, xx, yy, zz, s2, d2;
                ADD_X2(dx2, px2[j], ncx2);
                ADD_X2(dy2, py2[j], ncy2);
                ADD_X2(dz2, pz2[j], ncz2);
                MUL_X2(xx, dx2, dx2);
                MUL_X2(yy, dy2, dy2);
                MUL_X2(zz, dz2, dz2);
                ADD_X2(s2, xx, yy);
                ADD_X2(d2, s2, zz);
                float dlo, dhi;
                UNPACK_F32X2(dlo, dhi, d2);
                float m0 = fminf(dmin[2 * j], dlo);
                dmin[2 * j] = m0;
                if (m0 > bestv) { bestv = m0; bestk = 2 * j; }
                float m1 = fminf(dmin[2 * j + 1], dhi);
                dmin[2 * j + 1] = m1;
                if (m1 > bestv) { bestv = m1; bestk = 2 * j + 1; }
            }
            int besti = base + bestk * TFPS;

            unsigned vb   = __float_as_uint(bestv);
            unsigned wmax = __reduce_max_sync(0xffffffffu, vb);
            int cand = (vb == wmax) ? besti : 0x7fffffff;
            int wi   = __reduce_min_sync(0xffffffffu, cand);
            unsigned long long wkey =
                ((unsigned long long)wmax << 32)
              | ((unsigned long long)(0x3FFFu - (unsigned)wi) << 12)
              | (unsigned)it;

            if (lane < CLS) {
                asm volatile("st.relaxed.cluster.shared::cluster.b64 [%0], %1;"
                             :: "r"(a_remote + poff), "l"(wkey) : "memory");
            }

            unsigned long long k0, k1;
            for (;;) {
                k0 = lds_vol_u64(a_poll0 + poff);
                k1 = lds_vol_u64(a_poll1 + poff);
                bool ok = ((unsigned)(k0 & 0xFFFu) == (unsigned)it)
                       && ((unsigned)(k1 & 0xFFFu) == (unsigned)it);
                if (__all_sync(0xffffffffu, ok)) break;
            }
            unsigned long long k = (k0 > k1) ? k0 : k1;
            unsigned hi   = (unsigned)(k >> 32);
            unsigned gmax = __reduce_max_sync(0xffffffffu, hi);
            unsigned lo   = (hi == gmax) ? (unsigned)k : 0u;
            unsigned glo  = __reduce_max_sync(0xffffffffu, lo);
            int gidx = (int)(0x3FFFu - ((glo >> 12) & 0x3FFFu));

            if (rank == 0 && w == 0 && lane == 0) {
                g_idx[it] = gidx;
                asm volatile("st.relaxed.gpu.global.u32 [%0], %1;"
                             :: "l"(&g_flag[it]), "r"(eh | (unsigned)gidx) : "memory");
            }

            cx = s_x[gidx]; cy = s_y[gidx]; cz = s_z[gidx];
        }

        asm volatile("barrier.cluster.arrive.aligned;" ::: "memory");
        asm volatile("barrier.cluster.wait.aligned;"   ::: "memory");
    } else {
        // ================= consumer: ball query + MLP per center =================
        float* xb = dsm;                       // [32][68]
        float* h1 = xb + 32 * 68;              // [32][64]
        float* h2 = h1 + 32 * 64;              // [32][64]
        float* h3 = h2 + 32 * 64;              // [32][128]
        int*   s_ci  = (int*)(h3 + 32 * 128);  // [MAXC]
        float* s_cd  = (float*)(s_ci + MAXC);  // [MAXC]
        int*   s_sel = (int*)(s_cd + MAXC);    // [KNBR]
        int*   s_cnt = s_sel + KNBR;

        const int cons = blockIdx.x - CLS;

        for (int m = cons; m < MCTR; m += NCONS) {
            // wait for FPS to publish center m (epoch-tagged; replay-safe)
            unsigned f;
            int spins = 0;
            for (;;) {
                f = ldg_vol_u32(&g_flag[m]);
                if ((f & 0xFFFFC000u) == eh) break;
                if (++spins > 64) __nanosleep(200);
            }
            const int cidx = (int)(f & 0x3FFFu);
            const float cx = pos[cidx * 3 + 0];
            const float cy = pos[cidx * 3 + 1];
            const float cz = pos[cidx * 3 + 2];

            if (t == 0) *s_cnt = 0;
            __syncthreads();

            // ball query: 256 threads scan all points from L2
            for (int i = t; i < NPTS; i += TFPS) {
                float dx = pos[i * 3 + 0] - cx;
                float dy = pos[i * 3 + 1] - cy;
                float dz = pos[i * 3 + 2] - cz;
                float d2 = __fadd_rn(__fadd_rn(__fmul_rn(dx, dx), __fmul_rn(dy, dy)),
                                     __fmul_rn(dz, dz));
                bool in = (d2 <= RAD2);
                unsigned mk = __ballot_sync(0xffffffffu, in);
                int bslot = 0;
                if (lane == 0) bslot = atomicAdd(s_cnt, __popc(mk));
                bslot = __shfl_sync(0xffffffffu, bslot, 0)
                      + __popc(mk & ((1u << lane) - 1u));
                if (in && bslot < MAXC) { s_ci[bslot] = i; s_cd[bslot] = d2; }
            }
            __syncthreads();
            int cnt = min(*s_cnt, MAXC);
            int nsel;
            if (cnt <= KNBR) {
                nsel = cnt;
                if (t < cnt) s_sel[t] = s_ci[t];
            } else {
                nsel = KNBR;
                // exact nearest-32 by (d2, idx) rank — set-identical to top_k+mask
                if (t < cnt) {
                    float d = s_cd[t];
                    int  ii = s_ci[t];
                    int r = 0;
                    for (int o = 0; o < cnt; ++o) {
                        float d2o = s_cd[o];
                        r += (d2o < d) || (d2o == d && s_ci[o] < ii);
                    }
                    if (r < KNBR) s_sel[r] = ii;
                }
            }
            __syncthreads();

            // stage neighbor inputs
            for (int k = w; k < nsel; k += 8) {
                int j = s_sel[k];
                xb[k * 68 + lane]      = feat[j * FIN + lane];
                xb[k * 68 + lane + 32] = feat[j * FIN + lane + 32];
                if (lane == 0) {
                    xb[k * 68 + 64] = pos[j * 3 + 0] - cx;
                    xb[k * 68 + 65] = pos[j * 3 + 1] - cy;
                    xb[k * 68 + 66] = pos[j * 3 + 2] - cz;
                }
            }
            __syncthreads();

            for (int p = t; p < nsel * 64; p += TFPS) {
                int k = p >> 6, o = p & 63;
                float acc = b1[o];
                #pragma unroll
                for (int i = 0; i < 67; ++i)
                    acc = fmaf(xb[k * 68 + i], W1[i * 64 + o], acc);
                h1[k * 64 + o] = fmaxf(acc, 0.0f);
            }
            __syncthreads();

            for (int p = t; p < nsel * 64; p += TFPS) {
                int k = p >> 6, o = p & 63;
                float acc = b2[o];
                #pragma unroll
                for (int i = 0; i < 64; ++i)
                    acc = fmaf(h1[k * 64 + i], W2[i * 64 + o], acc);
                h2[k * 64 + o] = fmaxf(acc, 0.0f);
            }
            __syncthreads();

            for (int p = t; p < nsel * 128; p += TFPS) {
                int k = p >> 7, o = p & 127;
                float acc = b3[o];
                #pragma unroll
                for (int i = 0; i < 64; ++i)
                    acc = fmaf(h2[k * 64 + i], W3[i * 128 + o], acc);
                h3[k * 128 + o] = fmaxf(acc, 0.0f);
            }
            __syncthreads();

            if (t < 128) {
                float mx = -CUDART_INF_F;
                for (int k = 0; k < nsel; ++k) mx = fmaxf(mx, h3[k * 128 + t]);
                out[m * 128 + t] = mx;
            }
            __syncthreads();   // protect smem reuse next center
        }
    }
}

// ---------------- tail outputs ----------------
__global__ void tail_kernel(const float* __restrict__ pos, float* __restrict__ out,
                            int out_size)
{
    int m = blockIdx.x * blockDim.x + threadIdx.x;
    if (m >= MCTR) return;
    const int base = MCTR * 128;
    if (out_size >= base + 3 * MCTR) {
        int j = g_idx[m];
        out[base + 3 * m + 0] = pos[3 * j + 0];
        out[base + 3 * m + 1] = pos[3 * j + 1];
        out[base + 3 * m + 2] = pos[3 * j + 2];
    }
    if (out_size >= base + 3 * MCTR + MCTR) {
        out[base + 3 * MCTR + m] = 0.0f;
    }
}

extern "C" void kernel_launch(void* const* d_in, const int* in_sizes, int n_in,
                              void* d_out, int out_size)
{
    const float* feat = (const float*)d_in[0];
    const float* pos  = (const float*)d_in[1];
    const float* W1 = (const float*)d_in[3];
    const float* b1 = (const float*)d_in[4];
    const float* W2 = (const float*)d_in[5];
    const float* b2 = (const float*)d_in[6];
    const float* W3 = (const float*)d_in[7];
    const float* b3 = (const float*)d_in[8];
    float* out = (float*)d_out;

    const size_t fused_smem = 3 * NPTS * sizeof(float);   // 192KB
    cudaFuncSetAttribute(fused_kernel, cudaFuncAttributeMaxDynamicSharedMemorySize,
                         (int)fused_smem);

    epoch_kernel<<<1, 32>>>();
    fused_kernel<<<GRID, TFPS, fused_smem>>>(pos, feat, W1, b1, W2, b2, W3, b3, out);
    tail_kernel<<<(MCTR + 255) / 256, 256>>>(pos, out, out_size);
}